// round 4
// baseline (speedup 1.0000x reference)
#include <cuda_runtime.h>
#include <cstdint>

// minGRU bidirectional scan. R4: persistent CTAs + double-buffered TMA pipeline.
// x: [B, 512, L] fp32 -> out: [B, 256, L] fp32.
//   out channel c2 (0..255): rev = c2>=128, c = c2&127
//   h row = x[b, (rev?256:0)+c, :], gate row = h row + 128 channels.
// Recurrence (logical order; rev scans t = L-1..0):
//   out_t = a_t*out_{t-1} + b_t,  a = 1/(1+e^gate), b = (1-a)*g(h),
//   g(v) = v>=0 ? 1+v : e^v.
//
// Pipeline per CTA (1 CTA/SM, 1024 thr): input ring of 2 stages (h+g, 32KB each),
// output ring of 2 slots (32KB). Load seq i+2 overlaps compute of seq i; store
// of seq i-1 drains via bulk_group while seq i computes.

constexpr int L   = 8192;
constexpr int NT  = 1024;
constexpr int EPT = 8;     // NT * EPT == L
constexpr int NW  = NT / 32;

// smem floats: stage0{h,g} | stage1{h,g} | out0 | out1  = 6*L, then mbar[2], sA[32], sB[32]
constexpr int SMEM_FLOATS = 6 * L;
constexpr int SMEM_BYTES  = SMEM_FLOATS * 4 + 16 + 2 * NW * 4;

__device__ __forceinline__ float fast_rcp(float v) {
    float r;
    asm("rcp.approx.f32 %0, %1;" : "=f"(r) : "f"(v));
    return r;
}

__device__ __forceinline__ void mbar_wait(uint32_t mbar, uint32_t parity) {
    uint32_t done;
    asm volatile(
        "{\n\t.reg .pred p;\n\t"
        "mbarrier.try_wait.parity.shared::cta.b64 p, [%1], %2;\n\t"
        "selp.b32 %0, 1, 0, p;\n\t}"
        : "=r"(done) : "r"(mbar), "r"(parity) : "memory");
    while (!done) {
        asm volatile(
            "{\n\t.reg .pred p;\n\t"
            "mbarrier.try_wait.parity.shared::cta.b64 p, [%1], %2, 0x989680;\n\t"
            "selp.b32 %0, 1, 0, p;\n\t}"
            : "=r"(done) : "r"(mbar), "r"(parity) : "memory");
    }
}

__device__ __forceinline__ void bulk_load_seq(const float* __restrict__ x,
                                              int seq, uint32_t hdst, uint32_t gdst,
                                              uint32_t mbar) {
    const int b   = seq >> 8;
    const int c2  = seq & 255;
    const int hch = ((c2 & 128) ? 256 : 0) + (c2 & 127);
    const float* hrow = x + (size_t)(b * 512 + hch) * L;
    const float* grow = hrow + (size_t)128 * L;
    asm volatile("mbarrier.arrive.expect_tx.shared.b64 _, [%0], %1;"
                 :: "r"(mbar), "r"(2 * L * 4) : "memory");
    asm volatile("cp.async.bulk.shared::cta.global.mbarrier::complete_tx::bytes "
                 "[%0], [%1], %2, [%3];"
                 :: "r"(hdst), "l"(hrow), "r"(L * 4), "r"(mbar) : "memory");
    asm volatile("cp.async.bulk.shared::cta.global.mbarrier::complete_tx::bytes "
                 "[%0], [%1], %2, [%3];"
                 :: "r"(gdst), "l"(grow), "r"(L * 4), "r"(mbar) : "memory");
}

__global__ __launch_bounds__(NT, 1)
void mingru_bidir_kernel(const float* __restrict__ x, float* __restrict__ out,
                         int nseq) {
    extern __shared__ float smem[];
    // stage p: hbuf = smem + p*2L, gbuf = smem + p*2L + L; out slot p: smem + 4L + p*L
    uint64_t* mbar64 = (uint64_t*)(smem + SMEM_FLOATS);
    float* sA = (float*)(mbar64 + 2);
    float* sB = sA + NW;

    const int tid  = threadIdx.x;
    const int lane = tid & 31;
    const int warp = tid >> 5;
    const int r    = (tid >> 2) & 7;    // bank-conflict-free rotation
    const int G    = gridDim.x;

    const uint32_t smem_u32 = (uint32_t)__cvta_generic_to_shared(smem);
    const uint32_t mbar_u32 = (uint32_t)__cvta_generic_to_shared(mbar64);

    // number of sequences for this CTA
    const int n = (nseq - blockIdx.x + G - 1) / G;

    // ---- Prologue: init barriers, prefetch seq 0 (and 1) ----
    if (tid == 0) {
        asm volatile("mbarrier.init.shared.b64 [%0], 1;" :: "r"(mbar_u32) : "memory");
        asm volatile("mbarrier.init.shared.b64 [%0], 1;" :: "r"(mbar_u32 + 8) : "memory");
        bulk_load_seq(x, blockIdx.x, smem_u32, smem_u32 + L * 4, mbar_u32);
        if (n > 1)
            bulk_load_seq(x, blockIdx.x + G,
                          smem_u32 + 2 * L * 4, smem_u32 + 3 * L * 4, mbar_u32 + 8);
    }
    __syncthreads();

    for (int i = 0; i < n; ++i) {
        const int p = i & 1;
        const int seq = blockIdx.x + i * G;
        const float* hbuf = smem + p * 2 * L;
        const float* gbuf = hbuf + L;
        float* ob = smem + 4 * L + p * L;

        // ---- wait for input stage ----
        mbar_wait(mbar_u32 + 8 * p, (i >> 1) & 1);

        const bool rev = (seq & 128) != 0;
        const int base = tid * EPT;
        const int ibase = rev ? (L - 1 - base) : base;
        const int d = rev ? -1 : 1;

        // ---- pointwise + split chunk compose (arrival order, rotation r) ----
        // P1 = logical elems r..7 (arrive first), P2 = elems 0..r-1 (arrive last)
        float av[EPT], bv[EPT];
        float A1 = 1.0f, B1 = 0.0f, A2 = 1.0f, B2 = 0.0f;
        #pragma unroll
        for (int s = 0; s < EPT; ++s) {
            const int j = (s + r) & 7;
            const int idx = ibase + d * j;
            const float hh = hbuf[idx];
            const float gg = gbuf[idx];
            const float a  = fast_rcp(1.0f + __expf(gg));
            const float gh = (hh >= 0.0f) ? (1.0f + hh) : __expf(hh);
            const float bb = (1.0f - a) * gh;
            av[s] = a;
            bv[s] = bb;
            if (s < EPT - r) { B1 = fmaf(B1, a, bb); A1 *= a; }
            else             { B2 = fmaf(B2, a, bb); A2 *= a; }
        }
        float A_s = A1 * A2;
        float B_s = fmaf(A1, B2, B1);

        // ---- block scan of (A, B) affine maps ----
        #pragma unroll
        for (int off = 1; off < 32; off <<= 1) {
            const float Au = __shfl_up_sync(0xFFFFFFFFu, A_s, off);
            const float Bu = __shfl_up_sync(0xFFFFFFFFu, B_s, off);
            if (lane >= off) {
                B_s = fmaf(Bu, A_s, B_s);
                A_s = Au * A_s;
            }
        }
        float Ae = __shfl_up_sync(0xFFFFFFFFu, A_s, 1);
        float Be = __shfl_up_sync(0xFFFFFFFFu, B_s, 1);
        if (lane == 0) { Ae = 1.0f; Be = 0.0f; }

        if (lane == 31) { sA[warp] = A_s; sB[warp] = B_s; }
        // guard: store of seq i-2 (same out slot) must be done before we rewrite it
        if (tid == 0)
            asm volatile("cp.async.bulk.wait_group.read 1;" ::: "memory");
        __syncthreads();

        if (warp == 0) {
            float wa = sA[lane];
            float wb = sB[lane];
            #pragma unroll
            for (int off = 1; off < NW; off <<= 1) {
                const float Au = __shfl_up_sync(0xFFFFFFFFu, wa, off);
                const float Bu = __shfl_up_sync(0xFFFFFFFFu, wb, off);
                if (lane >= off) {
                    wb = fmaf(Bu, wa, wb);
                    wa = Au * wa;
                }
            }
            const float wae = __shfl_up_sync(0xFFFFFFFFu, wa, 1);
            const float wbe = __shfl_up_sync(0xFFFFFFFFu, wb, 1);
            sA[lane] = (lane == 0) ? 1.0f : wae;
            sB[lane] = (lane == 0) ? 0.0f : wbe;
        }
        __syncthreads();

        const float carry = fmaf(sB[warp], Ae, Be);

        // ---- replay (arrival order, two running states) + write out slot ----
        float s_lo = carry;                    // logical elems 0..r-1
        float s_hi = fmaf(A2, carry, B2);      // logical elems r..7
        #pragma unroll
        for (int s = 0; s < EPT; ++s) {
            const int j = (s + r) & 7;
            const int idx = ibase + d * j;
            float v;
            if (s < EPT - r) { s_hi = fmaf(av[s], s_hi, bv[s]); v = s_hi; }
            else             { s_lo = fmaf(av[s], s_lo, bv[s]); v = s_lo; }
            ob[idx] = v;
        }
        __syncthreads();

        // ---- store this seq; prefetch seq i+2 into the freed input stage ----
        if (tid == 0) {
            const int b  = seq >> 8;
            const int c2 = seq & 255;
            float* orow = out + (size_t)(b * 256 + c2) * L;
            asm volatile("fence.proxy.async.shared::cta;" ::: "memory");
            asm volatile("cp.async.bulk.global.shared::cta.bulk_group [%0], [%1], %2;"
                         :: "l"(orow),
                            "r"(smem_u32 + (4 + p) * L * 4), "r"(L * 4) : "memory");
            asm volatile("cp.async.bulk.commit_group;" ::: "memory");
            if (i + 2 < n)
                bulk_load_seq(x, seq + 2 * G,
                              smem_u32 + p * 2 * L * 4,
                              smem_u32 + (p * 2 + 1) * L * 4,
                              mbar_u32 + 8 * p);
        }
    }

    // drain outstanding stores before smem is released
    if (tid == 0)
        asm volatile("cp.async.bulk.wait_group.read 0;" ::: "memory");
}

extern "C" void kernel_launch(void* const* d_in, const int* in_sizes, int n_in,
                              void* d_out, int out_size) {
    const float* x = (const float*)d_in[0];
    float* out = (float*)d_out;
    const int B = in_sizes[0] / (512 * L);
    const int nseq = B * 256;

    int dev = 0, nsm = 148;
    cudaGetDevice(&dev);
    cudaDeviceGetAttribute(&nsm, cudaDevAttrMultiProcessorCount, dev);
    int G = nsm < nseq ? nsm : nseq;

    cudaFuncSetAttribute(mingru_bidir_kernel,
                         cudaFuncAttributeMaxDynamicSharedMemorySize, SMEM_BYTES);
    mingru_bidir_kernel<<<G, NT, SMEM_BYTES>>>(x, out, nseq);
}